// round 1
// baseline (speedup 1.0000x reference)
#include <cuda_runtime.h>
#include <math.h>

#define Bb 16
#define Ss 1024
#define Dd 512
#define Hh 512
#define Uu 512
#define MR (Bb*Ss)        // 16384 rows
#define G4U (4*Uu)        // 2048

// ---------------- scratch (device globals; no allocations allowed) ----------
__device__ float d_q[MR*Hh];
__device__ float d_k[MR*Hh];
__device__ float d_v[MR*Hh];
__device__ float d_scores[(size_t)Bb*Ss*Ss];
__device__ float d_ctx[MR*Hh];
__device__ float d_proj[MR*Uu];
__device__ float d_y1[MR*Uu];
__device__ float d_xp[(size_t)MR*G4U];
__device__ float d_hs[MR*Uu];
__device__ float d_hbuf[2][Bb*Uu];
__device__ int   d_flags[128];
__device__ int   d_go;

// ---------------- generic fp32 SGEMM: C = alpha * A * op(B) (+bias) ---------
// A: [M,K] row-major. TB==0: B [K,N] row-major. TB==1: B [N,K] row-major (B^T).
// 128x128 tile, Ktile=8, 256 threads, 8x8 per-thread microtile.
template<int TB>
__global__ __launch_bounds__(256) void sgemm(
    const float* __restrict__ Ag, const float* __restrict__ Bg,
    float* __restrict__ Cg, const float* __restrict__ bias,
    int M, int N, int K, long sA, long sB, long sC, float alpha)
{
    const float* A  = Ag + (long)blockIdx.z * sA;
    const float* Bm = Bg + (long)blockIdx.z * sB;
    float*       C  = Cg + (long)blockIdx.z * sC;

    __shared__ float As[8][128];
    __shared__ float Bs[8][128];

    int tid = threadIdx.x;
    int m0 = blockIdx.y * 128, n0 = blockIdx.x * 128;
    int tx = tid & 15, ty = tid >> 4;

    float acc[8][8];
#pragma unroll
    for (int i = 0; i < 8; i++)
#pragma unroll
        for (int j = 0; j < 8; j++) acc[i][j] = 0.f;

    int arow = tid >> 1, akc = (tid & 1) * 4;

    float4 av, bv;
    av = *(const float4*)&A[(long)(m0 + arow) * K + akc];
    if (TB == 0)
        bv = *(const float4*)&Bm[(long)(tid >> 5) * N + n0 + (tid & 31) * 4];
    else
        bv = *(const float4*)&Bm[(long)(n0 + (tid >> 1)) * K + (tid & 1) * 4];

    for (int k0 = 0; k0 < K; k0 += 8) {
        As[akc + 0][arow] = av.x; As[akc + 1][arow] = av.y;
        As[akc + 2][arow] = av.z; As[akc + 3][arow] = av.w;
        if (TB == 0) {
            *(float4*)&Bs[tid >> 5][(tid & 31) * 4] = bv;
        } else {
            int bn = tid >> 1, c0 = (tid & 1) * 4;
            Bs[c0 + 0][bn] = bv.x; Bs[c0 + 1][bn] = bv.y;
            Bs[c0 + 2][bn] = bv.z; Bs[c0 + 3][bn] = bv.w;
        }
        __syncthreads();

        int k1 = k0 + 8;
        if (k1 < K) {
            av = *(const float4*)&A[(long)(m0 + arow) * K + k1 + akc];
            if (TB == 0)
                bv = *(const float4*)&Bm[(long)(k1 + (tid >> 5)) * N + n0 + (tid & 31) * 4];
            else
                bv = *(const float4*)&Bm[(long)(n0 + (tid >> 1)) * K + k1 + (tid & 1) * 4];
        }

#pragma unroll
        for (int k = 0; k < 8; k++) {
            float a[8], b[8];
            *(float4*)&a[0] = *(const float4*)&As[k][ty * 4];
            *(float4*)&a[4] = *(const float4*)&As[k][64 + ty * 4];
            *(float4*)&b[0] = *(const float4*)&Bs[k][tx * 4];
            *(float4*)&b[4] = *(const float4*)&Bs[k][64 + tx * 4];
#pragma unroll
            for (int i = 0; i < 8; i++)
#pragma unroll
                for (int j = 0; j < 8; j++) acc[i][j] += a[i] * b[j];
        }
        __syncthreads();
    }

#pragma unroll
    for (int i = 0; i < 8; i++) {
        int r = m0 + ((i < 4) ? (ty * 4 + i) : (64 + ty * 4 + i - 4));
#pragma unroll
        for (int jh = 0; jh < 2; jh++) {
            int c = n0 + jh * 64 + tx * 4;
            float4 o;
            o.x = alpha * acc[i][jh * 4 + 0];
            o.y = alpha * acc[i][jh * 4 + 1];
            o.z = alpha * acc[i][jh * 4 + 2];
            o.w = alpha * acc[i][jh * 4 + 3];
            if (bias) {
                o.x += bias[c + 0]; o.y += bias[c + 1];
                o.z += bias[c + 2]; o.w += bias[c + 3];
            }
            *(float4*)&C[(long)r * N + c] = o;
        }
    }
}

// ---------------- softmax over rows of length 1024 ---------------------------
__global__ __launch_bounds__(256) void softmax_k(float* __restrict__ s)
{
    __shared__ float red[8];
    long row = blockIdx.x;
    float* p = s + row * 1024;
    int tid = threadIdx.x;
    float4 v = ((float4*)p)[tid];

    float m = fmaxf(fmaxf(v.x, v.y), fmaxf(v.z, v.w));
#pragma unroll
    for (int o = 16; o; o >>= 1) m = fmaxf(m, __shfl_xor_sync(~0u, m, o));
    if ((tid & 31) == 0) red[tid >> 5] = m;
    __syncthreads();
    m = red[0];
#pragma unroll
    for (int i = 1; i < 8; i++) m = fmaxf(m, red[i]);

    v.x = expf(v.x - m); v.y = expf(v.y - m);
    v.z = expf(v.z - m); v.w = expf(v.w - m);
    float su = v.x + v.y + v.z + v.w;
#pragma unroll
    for (int o = 16; o; o >>= 1) su += __shfl_xor_sync(~0u, su, o);
    __syncthreads();
    if ((tid & 31) == 0) red[tid >> 5] = su;
    __syncthreads();
    su = 0.f;
#pragma unroll
    for (int i = 0; i < 8; i++) su += red[i];
    float inv = 1.f / su;
    v.x *= inv; v.y *= inv; v.z *= inv; v.w *= inv;
    ((float4*)p)[tid] = v;
}

// ---------------- fused residual add + LayerNorm (row len 512) --------------
__global__ __launch_bounds__(128) void ln_add_k(
    const float* __restrict__ a, const float* __restrict__ b,
    const float* __restrict__ gamma, const float* __restrict__ beta,
    float* __restrict__ out)
{
    __shared__ float red[4];
    long row = blockIdx.x;
    int tid = threadIdx.x;
    float4 x = ((const float4*)(a + row * 512))[tid];
    float4 y = ((const float4*)(b + row * 512))[tid];
    x.x += y.x; x.y += y.y; x.z += y.z; x.w += y.w;

    float su = x.x + x.y + x.z + x.w;
#pragma unroll
    for (int o = 16; o; o >>= 1) su += __shfl_xor_sync(~0u, su, o);
    if ((tid & 31) == 0) red[tid >> 5] = su;
    __syncthreads();
    su = red[0] + red[1] + red[2] + red[3];
    float mu = su * (1.f / 512.f);

    float4 dx;
    dx.x = x.x - mu; dx.y = x.y - mu; dx.z = x.z - mu; dx.w = x.w - mu;
    float sq = dx.x * dx.x + dx.y * dx.y + dx.z * dx.z + dx.w * dx.w;
#pragma unroll
    for (int o = 16; o; o >>= 1) sq += __shfl_xor_sync(~0u, sq, o);
    __syncthreads();
    if ((tid & 31) == 0) red[tid >> 5] = sq;
    __syncthreads();
    sq = red[0] + red[1] + red[2] + red[3];
    float inv = rsqrtf(sq * (1.f / 512.f) + 1e-3f);

    float4 g = ((const float4*)gamma)[tid];
    float4 bt = ((const float4*)beta)[tid];
    float4 o4;
    o4.x = g.x * dx.x * inv + bt.x;
    o4.y = g.y * dx.y * inv + bt.y;
    o4.z = g.z * dx.z * inv + bt.z;
    o4.w = g.w * dx.w * inv + bt.w;
    ((float4*)(out + row * 512))[tid] = o4;
}

// ---------------- reset for persistent LSTM sync state ----------------------
__global__ void reset_k()
{
    int tid = threadIdx.x + blockIdx.x * blockDim.x;
    if (tid < Bb * Uu) { d_hbuf[0][tid] = 0.f; d_hbuf[1][tid] = 0.f; }
    if (tid < 128) d_flags[tid] = 0;
    if (tid == 0) d_go = 0;
}

// ---------------- persistent LSTM scan --------------------------------------
// 128 CTAs x 128 threads. CTA owns 4 u-columns -> 16 gate cols of R in smem.
// Double-buffered h in d_hbuf -> exactly one grid barrier per timestep.
#define LSTM_SMEM ((16*516 + 16*512)*4)

__global__ __launch_bounds__(128) void lstm_k(
    const float* __restrict__ xp, const float* __restrict__ R,
    float* __restrict__ hs)
{
    extern __shared__ float sm[];
    float* Rs  = sm;            // [16][516] padded
    float* h_s = sm + 16 * 516; // [16][512]
    __shared__ float z_s[16][17];
    __shared__ float c_s[4][17];

    int tid = threadIdx.x;
    int cta = blockIdx.x;
    int u0 = cta * 4;

    // Load this CTA's 16 columns of the recurrent kernel (coalesced-ish).
    for (int idx = tid; idx < 8192; idx += 128) {
        int k = idx >> 4, lc = idx & 15;
        Rs[lc * 516 + k] = R[(long)k * 2048 + (lc >> 2) * 512 + u0 + (lc & 3)];
    }
    if (tid < 64) c_s[tid >> 4][tid & 15] = 0.f;

    int lc = tid & 15;
    int b0 = (tid >> 4) * 2;
    int gcol = (lc >> 2) * 512 + u0 + (lc & 3);
    const float* xpa = xp + (long)b0 * Ss * 2048 + gcol;
    const float* xpb = xpa + (long)Ss * 2048;
    const float4* r4 = (const float4*)(Rs + lc * 516);
    const float4* ha = (const float4*)(h_s + b0 * 512);
    const float4* hb = (const float4*)(h_s + b0 * 512 + 512);
    float4* hd = (float4*)h_s;

    __syncthreads();

    for (int t = 0; t < 1024; t++) {
        float xv0 = xpa[(long)t * 2048];
        float xv1 = xpb[(long)t * 2048];

        // load h_{t-1} (double buffer; t=0 reads zeros)
        const float4* hg = (const float4*)(d_hbuf[(t + 1) & 1]);
#pragma unroll
        for (int i = 0; i < 16; i++) hd[tid + i * 128] = hg[tid + i * 128];
        __syncthreads();

        // z[b][col] = xp + h . R[:,col]  (each thread: 2 batches, 1 col)
        float s0 = 0, s1 = 0, s2 = 0, s3 = 0, t0 = 0, t1 = 0, t2 = 0, t3 = 0;
#pragma unroll 8
        for (int k4 = 0; k4 < 128; k4++) {
            float4 r = r4[k4], p = ha[k4], q = hb[k4];
            s0 += r.x * p.x; s1 += r.y * p.y; s2 += r.z * p.z; s3 += r.w * p.w;
            t0 += r.x * q.x; t1 += r.y * q.y; t2 += r.z * q.z; t3 += r.w * q.w;
        }
        z_s[lc][b0]     = xv0 + (s0 + s1) + (s2 + s3);
        z_s[lc][b0 + 1] = xv1 + (t0 + t1) + (t2 + t3);
        __syncthreads();

        // gate math: 64 threads, one (u,b) each
        if (tid < 64) {
            int du = tid >> 4, b = tid & 15;
            float zi = z_s[du][b], zf = z_s[4 + du][b];
            float zg = z_s[8 + du][b], zo = z_s[12 + du][b];
            float si = 1.f / (1.f + expf(-zi));
            float sf = 1.f / (1.f + expf(-zf));
            float so = 1.f / (1.f + expf(-zo));
            float c = sf * c_s[du][b] + si * fmaxf(zg, 0.f);
            c_s[du][b] = c;
            float h = so * fmaxf(c, 0.f);
            d_hbuf[t & 1][b * 512 + u0 + du] = h;
            hs[(long)b * Ss * 512 + (long)t * 512 + u0 + du] = h;
        }
        __syncthreads();

        // ---- grid barrier (flags + go; all 128 CTAs are co-resident) ----
        if (tid == 0) { __threadfence(); ((volatile int*)d_flags)[cta] = t + 1; }
        if (cta == 0) {
            while (((volatile int*)d_flags)[tid] < t + 1) __nanosleep(32);
            __syncthreads();
            if (tid == 0) { __threadfence(); *((volatile int*)&d_go) = t + 1; }
        }
        if (tid == 0) {
            while (*((volatile int*)&d_go) < t + 1) __nanosleep(32);
            __threadfence();
        }
        __syncthreads();
    }
}

// ---------------- launch ------------------------------------------------------
extern "C" void kernel_launch(void* const* d_in, const int* in_sizes, int n_in,
                              void* d_out, int out_size)
{
    const float* emb   = (const float*)d_in[0];
    const float* Wq    = (const float*)d_in[1];
    const float* Wk    = (const float*)d_in[2];
    const float* Wv    = (const float*)d_in[3];
    const float* Wo    = (const float*)d_in[4];
    const float* gamma = (const float*)d_in[5];
    const float* beta  = (const float*)d_in[6];
    const float* lk    = (const float*)d_in[7];
    const float* lrk   = (const float*)d_in[8];
    const float* lb    = (const float*)d_in[9];

    float *q, *k, *v, *sc, *ctx, *proj, *y1, *xp, *hs;
    cudaGetSymbolAddress((void**)&q,    d_q);
    cudaGetSymbolAddress((void**)&k,    d_k);
    cudaGetSymbolAddress((void**)&v,    d_v);
    cudaGetSymbolAddress((void**)&sc,   d_scores);
    cudaGetSymbolAddress((void**)&ctx,  d_ctx);
    cudaGetSymbolAddress((void**)&proj, d_proj);
    cudaGetSymbolAddress((void**)&y1,   d_y1);
    cudaGetSymbolAddress((void**)&xp,   d_xp);
    cudaGetSymbolAddress((void**)&hs,   d_hs);

    const float sc_alpha = 0.044194173824159216f; // 1/sqrt(512)

    // Q, K, V
    sgemm<0><<<dim3(4, 128, 1), 256>>>(emb, Wq, q, nullptr, MR, Hh, Dd, 0, 0, 0, 1.f);
    sgemm<0><<<dim3(4, 128, 1), 256>>>(emb, Wk, k, nullptr, MR, Hh, Dd, 0, 0, 0, 1.f);
    sgemm<0><<<dim3(4, 128, 1), 256>>>(emb, Wv, v, nullptr, MR, Hh, Dd, 0, 0, 0, 1.f);

    // scores = Q K^T / sqrt(H)   (batched NT)
    sgemm<1><<<dim3(8, 8, 16), 256>>>(q, k, sc, nullptr, Ss, Ss, Hh,
                                      (long)Ss * Hh, (long)Ss * Hh, (long)Ss * Ss, sc_alpha);
    softmax_k<<<Bb * Ss, 256>>>(sc);

    // ctx = attn V   (batched NN)
    sgemm<0><<<dim3(4, 8, 16), 256>>>(sc, v, ctx, nullptr, Ss, Hh, Ss,
                                      (long)Ss * Ss, (long)Ss * Hh, (long)Ss * Hh, 1.f);

    // out-proj + residual LN
    sgemm<0><<<dim3(4, 128, 1), 256>>>(ctx, Wo, proj, nullptr, MR, Uu, Hh, 0, 0, 0, 1.f);
    ln_add_k<<<MR, 128>>>(proj, emb, gamma, beta, y1);

    // LSTM input projection (+bias)
    sgemm<0><<<dim3(16, 128, 1), 256>>>(y1, lk, xp, lb, MR, G4U, Uu, 0, 0, 0, 1.f);

    // persistent LSTM scan
    reset_k<<<32, 256>>>();
    cudaFuncSetAttribute(lstm_k, cudaFuncAttributeMaxDynamicSharedMemorySize, LSTM_SMEM);
    lstm_k<<<128, 128, LSTM_SMEM>>>(xp, lrk, hs);

    // final residual LN -> output
    ln_add_k<<<MR, 128>>>(hs, y1, gamma, beta, (float*)d_out);
}

// round 2
// speedup vs baseline: 1.3865x; 1.3865x over previous
#include <cuda_runtime.h>
#include <math.h>

#define Bb 16
#define Ss 1024
#define Dd 512
#define Hh 512
#define Uu 512
#define MR (Bb*Ss)        // 16384 rows
#define G4U (4*Uu)        // 2048

// ---------------- scratch (device globals; no allocations allowed) ----------
__device__ float d_q[MR*Hh];
__device__ float d_k[MR*Hh];
__device__ float d_v[MR*Hh];
__device__ float d_scores[(size_t)Bb*Ss*Ss];
__device__ float d_ctx[MR*Hh];
__device__ float d_proj[MR*Uu];
__device__ float d_y1[MR*Uu];
__device__ float d_xp[(size_t)MR*G4U];
__device__ float d_hs[MR*Uu];
__device__ float d_hbuf[2][Bb*Uu];
__device__ int   d_cnt;

// ---------------- generic fp32 SGEMM: C = alpha * A * op(B) (+bias) ---------
template<int TB>
__global__ __launch_bounds__(256) void sgemm(
    const float* __restrict__ Ag, const float* __restrict__ Bg,
    float* __restrict__ Cg, const float* __restrict__ bias,
    int M, int N, int K, long sA, long sB, long sC, float alpha)
{
    const float* A  = Ag + (long)blockIdx.z * sA;
    const float* Bm = Bg + (long)blockIdx.z * sB;
    float*       C  = Cg + (long)blockIdx.z * sC;

    __shared__ float As[8][128];
    __shared__ float Bs[8][128];

    int tid = threadIdx.x;
    int m0 = blockIdx.y * 128, n0 = blockIdx.x * 128;
    int tx = tid & 15, ty = tid >> 4;

    float acc[8][8];
#pragma unroll
    for (int i = 0; i < 8; i++)
#pragma unroll
        for (int j = 0; j < 8; j++) acc[i][j] = 0.f;

    int arow = tid >> 1, akc = (tid & 1) * 4;

    float4 av, bv;
    av = *(const float4*)&A[(long)(m0 + arow) * K + akc];
    if (TB == 0)
        bv = *(const float4*)&Bm[(long)(tid >> 5) * N + n0 + (tid & 31) * 4];
    else
        bv = *(const float4*)&Bm[(long)(n0 + (tid >> 1)) * K + (tid & 1) * 4];

    for (int k0 = 0; k0 < K; k0 += 8) {
        As[akc + 0][arow] = av.x; As[akc + 1][arow] = av.y;
        As[akc + 2][arow] = av.z; As[akc + 3][arow] = av.w;
        if (TB == 0) {
            *(float4*)&Bs[tid >> 5][(tid & 31) * 4] = bv;
        } else {
            int bn = tid >> 1, c0 = (tid & 1) * 4;
            Bs[c0 + 0][bn] = bv.x; Bs[c0 + 1][bn] = bv.y;
            Bs[c0 + 2][bn] = bv.z; Bs[c0 + 3][bn] = bv.w;
        }
        __syncthreads();

        int k1 = k0 + 8;
        if (k1 < K) {
            av = *(const float4*)&A[(long)(m0 + arow) * K + k1 + akc];
            if (TB == 0)
                bv = *(const float4*)&Bm[(long)(k1 + (tid >> 5)) * N + n0 + (tid & 31) * 4];
            else
                bv = *(const float4*)&Bm[(long)(n0 + (tid >> 1)) * K + k1 + (tid & 1) * 4];
        }

#pragma unroll
        for (int k = 0; k < 8; k++) {
            float a[8], b[8];
            *(float4*)&a[0] = *(const float4*)&As[k][ty * 4];
            *(float4*)&a[4] = *(const float4*)&As[k][64 + ty * 4];
            *(float4*)&b[0] = *(const float4*)&Bs[k][tx * 4];
            *(float4*)&b[4] = *(const float4*)&Bs[k][64 + tx * 4];
#pragma unroll
            for (int i = 0; i < 8; i++)
#pragma unroll
                for (int j = 0; j < 8; j++) acc[i][j] += a[i] * b[j];
        }
        __syncthreads();
    }

#pragma unroll
    for (int i = 0; i < 8; i++) {
        int r = m0 + ((i < 4) ? (ty * 4 + i) : (64 + ty * 4 + i - 4));
#pragma unroll
        for (int jh = 0; jh < 2; jh++) {
            int c = n0 + jh * 64 + tx * 4;
            float4 o;
            o.x = alpha * acc[i][jh * 4 + 0];
            o.y = alpha * acc[i][jh * 4 + 1];
            o.z = alpha * acc[i][jh * 4 + 2];
            o.w = alpha * acc[i][jh * 4 + 3];
            if (bias) {
                o.x += bias[c + 0]; o.y += bias[c + 1];
                o.z += bias[c + 2]; o.w += bias[c + 3];
            }
            *(float4*)&C[(long)r * N + c] = o;
        }
    }
}

// ---------------- softmax over rows of length 1024 ---------------------------
__global__ __launch_bounds__(256) void softmax_k(float* __restrict__ s)
{
    __shared__ float red[8];
    long row = blockIdx.x;
    float* p = s + row * 1024;
    int tid = threadIdx.x;
    float4 v = ((float4*)p)[tid];

    float m = fmaxf(fmaxf(v.x, v.y), fmaxf(v.z, v.w));
#pragma unroll
    for (int o = 16; o; o >>= 1) m = fmaxf(m, __shfl_xor_sync(~0u, m, o));
    if ((tid & 31) == 0) red[tid >> 5] = m;
    __syncthreads();
    m = red[0];
#pragma unroll
    for (int i = 1; i < 8; i++) m = fmaxf(m, red[i]);

    v.x = expf(v.x - m); v.y = expf(v.y - m);
    v.z = expf(v.z - m); v.w = expf(v.w - m);
    float su = v.x + v.y + v.z + v.w;
#pragma unroll
    for (int o = 16; o; o >>= 1) su += __shfl_xor_sync(~0u, su, o);
    __syncthreads();
    if ((tid & 31) == 0) red[tid >> 5] = su;
    __syncthreads();
    su = 0.f;
#pragma unroll
    for (int i = 0; i < 8; i++) su += red[i];
    float inv = 1.f / su;
    v.x *= inv; v.y *= inv; v.z *= inv; v.w *= inv;
    ((float4*)p)[tid] = v;
}

// ---------------- fused residual add + LayerNorm (row len 512) --------------
__global__ __launch_bounds__(128) void ln_add_k(
    const float* __restrict__ a, const float* __restrict__ b,
    const float* __restrict__ gamma, const float* __restrict__ beta,
    float* __restrict__ out)
{
    __shared__ float red[4];
    long row = blockIdx.x;
    int tid = threadIdx.x;
    float4 x = ((const float4*)(a + row * 512))[tid];
    float4 y = ((const float4*)(b + row * 512))[tid];
    x.x += y.x; x.y += y.y; x.z += y.z; x.w += y.w;

    float su = x.x + x.y + x.z + x.w;
#pragma unroll
    for (int o = 16; o; o >>= 1) su += __shfl_xor_sync(~0u, su, o);
    if ((tid & 31) == 0) red[tid >> 5] = su;
    __syncthreads();
    su = red[0] + red[1] + red[2] + red[3];
    float mu = su * (1.f / 512.f);

    float4 dx;
    dx.x = x.x - mu; dx.y = x.y - mu; dx.z = x.z - mu; dx.w = x.w - mu;
    float sq = dx.x * dx.x + dx.y * dx.y + dx.z * dx.z + dx.w * dx.w;
#pragma unroll
    for (int o = 16; o; o >>= 1) sq += __shfl_xor_sync(~0u, sq, o);
    __syncthreads();
    if ((tid & 31) == 0) red[tid >> 5] = sq;
    __syncthreads();
    sq = red[0] + red[1] + red[2] + red[3];
    float inv = rsqrtf(sq * (1.f / 512.f) + 1e-3f);

    float4 g = ((const float4*)gamma)[tid];
    float4 bt = ((const float4*)beta)[tid];
    float4 o4;
    o4.x = g.x * dx.x * inv + bt.x;
    o4.y = g.y * dx.y * inv + bt.y;
    o4.z = g.z * dx.z * inv + bt.z;
    o4.w = g.w * dx.w * inv + bt.w;
    ((float4*)(out + row * 512))[tid] = o4;
}

// ---------------- reset for persistent LSTM sync state ----------------------
__global__ void reset_k()
{
    int tid = threadIdx.x + blockIdx.x * blockDim.x;
    if (tid < Bb * Uu) { d_hbuf[0][tid] = 0.f; d_hbuf[1][tid] = 0.f; }
    if (tid == 0) d_cnt = 0;
}

// ---------------- persistent LSTM scan --------------------------------------
// 256 CTAs x 128 threads (2 CTAs/SM, single wave on 148 SMs).
// CTA (cg, bh): cg = cta>>1 owns u's [cg*4, cg*4+4) -> 16 gate cols;
//               bh = cta&1 owns batches [bh*8, bh*8+8).
// R slice transposed in smem Rs[k][16]; h staged as h_s[k][b] (stride 10).
// Thread = (cq: 4 cols, bq: 2 batches, ks: 64-k slice).
// One global barrier per step (monotonic counter), double-buffered h.
#define LSTM_NCTA 256
#define LSTM_DSMEM ((512*16 + 512*10) * 4)

__global__ __launch_bounds__(128) void lstm_k(
    const float* __restrict__ xp, const float* __restrict__ R,
    float* __restrict__ hs)
{
    extern __shared__ float sm[];
    float* Rs  = sm;            // [512][16]
    float* h_s = sm + 512 * 16; // [512][10] (stride 10 to dodge bank conflicts)
    __shared__ float z_part[8][16][8];
    __shared__ float z_s[16][9];
    __shared__ float c_s[4][9];

    const int tid = threadIdx.x;
    const int cta = blockIdx.x;
    const int cg  = cta >> 1;
    const int bh  = cta & 1;
    const int u0  = cg * 4;
    const int b0  = bh * 8;

    // Load R slice transposed: Rs[k][c], c = g*4 + du -> global col g*512+u0+du
    for (int idx = tid; idx < 8192; idx += 128) {
        int k = idx >> 4, c = idx & 15;
        Rs[k * 16 + c] = R[(long)k * 2048 + (c >> 2) * 512 + u0 + (c & 3)];
    }
    if (tid < 32) c_s[tid >> 3][tid & 7] = 0.f;

    const int cq = tid & 3;
    const int bq = (tid >> 2) & 3;
    const int ks = tid >> 4;
    const float* rp0 = Rs + ks * 64 * 16 + cq * 4;
    const float* hp0 = h_s + ks * 64 * 10 + bq * 2;

    // reducer identity: one (col, batch) per thread
    const int rc = tid >> 3;
    const int rb = tid & 7;
    const float* xp_t = xp + (long)(b0 + rb) * Ss * 2048
                           + (rc >> 2) * 512 + u0 + (rc & 3);

    __syncthreads();

    for (int t = 0; t < 1024; t++) {
        // prefetch xp operand for this step (no dependency on barrier)
        float xv = __ldg(xp_t + (long)t * 2048);

        // ---- wait for all step-(t-1) writes ----
        if (t > 0) {
            if (tid == 0) {
                while (*((volatile int*)&d_cnt) < LSTM_NCTA * t) { }
                __threadfence();
            }
            __syncthreads();
        }

        // ---- stage h_{t-1} for our 8 batches into smem (transposed) ----
        const float* hg = d_hbuf[(t + 1) & 1] + (long)b0 * 512;
        for (int i = tid; i < 1024; i += 128) {
            float4 v = ((const float4*)hg)[i];
            int b = i >> 7;
            int k = (i & 127) * 4;
            h_s[(k + 0) * 10 + b] = v.x;
            h_s[(k + 1) * 10 + b] = v.y;
            h_s[(k + 2) * 10 + b] = v.z;
            h_s[(k + 3) * 10 + b] = v.w;
        }
        __syncthreads();

        // ---- partial dot products: 4 cols x 2 batches x 64 k per thread ----
        float a0 = 0, a1 = 0, a2 = 0, a3 = 0;
        float e0 = 0, e1 = 0, e2 = 0, e3 = 0;
#pragma unroll 16
        for (int k = 0; k < 64; k++) {
            float4 r  = *(const float4*)(rp0 + k * 16);
            float2 h2 = *(const float2*)(hp0 + k * 10);
            a0 += r.x * h2.x; a1 += r.y * h2.x;
            a2 += r.z * h2.x; a3 += r.w * h2.x;
            e0 += r.x * h2.y; e1 += r.y * h2.y;
            e2 += r.z * h2.y; e3 += r.w * h2.y;
        }
        {
            int c0 = cq * 4, bb = bq * 2;
            z_part[ks][c0 + 0][bb]     = a0;
            z_part[ks][c0 + 1][bb]     = a1;
            z_part[ks][c0 + 2][bb]     = a2;
            z_part[ks][c0 + 3][bb]     = a3;
            z_part[ks][c0 + 0][bb + 1] = e0;
            z_part[ks][c0 + 1][bb + 1] = e1;
            z_part[ks][c0 + 2][bb + 1] = e2;
            z_part[ks][c0 + 3][bb + 1] = e3;
        }
        __syncthreads();

        // ---- reduce 8 k-slices + xp ----
        {
            float z = xv;
#pragma unroll
            for (int s = 0; s < 8; s++) z += z_part[s][rc][rb];
            z_s[rc][rb] = z;
        }
        __syncthreads();

        // ---- gate math: 32 threads, one (u, b) each ----
        if (tid < 32) {
            int du = tid >> 3, b = tid & 7;
            float zi = z_s[du][b],      zf = z_s[4 + du][b];
            float zg = z_s[8 + du][b],  zo = z_s[12 + du][b];
            float si = 1.f / (1.f + expf(-zi));
            float sf = 1.f / (1.f + expf(-zf));
            float so = 1.f / (1.f + expf(-zo));
            float c  = sf * c_s[du][b] + si * fmaxf(zg, 0.f);
            c_s[du][b] = c;
            float h = so * fmaxf(c, 0.f);
            int gb = b0 + b;
            d_hbuf[t & 1][gb * 512 + u0 + du] = h;
            hs[((long)gb * Ss + t) * 512 + u0 + du] = h;
        }
        __syncthreads();

        // ---- signal step t done ----
        if (tid == 0) { __threadfence(); atomicAdd(&d_cnt, 1); }
    }
}

// ---------------- launch ------------------------------------------------------
extern "C" void kernel_launch(void* const* d_in, const int* in_sizes, int n_in,
                              void* d_out, int out_size)
{
    const float* emb   = (const float*)d_in[0];
    const float* Wq    = (const float*)d_in[1];
    const float* Wk    = (const float*)d_in[2];
    const float* Wv    = (const float*)d_in[3];
    const float* Wo    = (const float*)d_in[4];
    const float* gamma = (const float*)d_in[5];
    const float* beta  = (const float*)d_in[6];
    const float* lk    = (const float*)d_in[7];
    const float* lrk   = (const float*)d_in[8];
    const float* lb    = (const float*)d_in[9];

    float *q, *k, *v, *sc, *ctx, *proj, *y1, *xp, *hs;
    cudaGetSymbolAddress((void**)&q,    d_q);
    cudaGetSymbolAddress((void**)&k,    d_k);
    cudaGetSymbolAddress((void**)&v,    d_v);
    cudaGetSymbolAddress((void**)&sc,   d_scores);
    cudaGetSymbolAddress((void**)&ctx,  d_ctx);
    cudaGetSymbolAddress((void**)&proj, d_proj);
    cudaGetSymbolAddress((void**)&y1,   d_y1);
    cudaGetSymbolAddress((void**)&xp,   d_xp);
    cudaGetSymbolAddress((void**)&hs,   d_hs);

    const float sc_alpha = 0.044194173824159216f; // 1/sqrt(512)

    // Q, K, V
    sgemm<0><<<dim3(4, 128, 1), 256>>>(emb, Wq, q, nullptr, MR, Hh, Dd, 0, 0, 0, 1.f);
    sgemm<0><<<dim3(4, 128, 1), 256>>>(emb, Wk, k, nullptr, MR, Hh, Dd, 0, 0, 0, 1.f);
    sgemm<0><<<dim3(4, 128, 1), 256>>>(emb, Wv, v, nullptr, MR, Hh, Dd, 0, 0, 0, 1.f);

    // scores = Q K^T / sqrt(H)   (batched NT)
    sgemm<1><<<dim3(8, 8, 16), 256>>>(q, k, sc, nullptr, Ss, Ss, Hh,
                                      (long)Ss * Hh, (long)Ss * Hh, (long)Ss * Ss, sc_alpha);
    softmax_k<<<Bb * Ss, 256>>>(sc);

    // ctx = attn V   (batched NN)
    sgemm<0><<<dim3(4, 8, 16), 256>>>(sc, v, ctx, nullptr, Ss, Hh, Ss,
                                      (long)Ss * Ss, (long)Ss * Hh, (long)Ss * Hh, 1.f);

    // out-proj + residual LN
    sgemm<0><<<dim3(4, 128, 1), 256>>>(ctx, Wo, proj, nullptr, MR, Uu, Hh, 0, 0, 0, 1.f);
    ln_add_k<<<MR, 128>>>(proj, emb, gamma, beta, y1);

    // LSTM input projection (+bias)
    sgemm<0><<<dim3(16, 128, 1), 256>>>(y1, lk, xp, lb, MR, G4U, Uu, 0, 0, 0, 1.f);

    // persistent LSTM scan
    reset_k<<<32, 256>>>();
    cudaFuncSetAttribute(lstm_k, cudaFuncAttributeMaxDynamicSharedMemorySize, LSTM_DSMEM);
    lstm_k<<<LSTM_NCTA, 128, LSTM_DSMEM>>>(xp, lrk, hs);

    // final residual LN -> output
    ln_add_k<<<MR, 128>>>(hs, y1, gamma, beta, (float*)d_out);
}